// round 2
// baseline (speedup 1.0000x reference)
#include <cuda_runtime.h>
#include <cstdint>

// AtteMatchLay: cos = <r*m, w2> / (max(||r||_w2,eps) * max(||m||_w2,eps))
// shapes: repres/max_att [16,512,768] f32, weight [20,768] f32, out [16,512,20] f32
//
// Strategy: packed f32x2 FFMA (FFMA2) — 2 adjacent p-outputs per instruction.
// 30 f32x2 accumulators per thread (dot, rr, mm) x 10 p-pairs.
// Block = 256 threads = 32 rows x 8 D-segments; per-chunk smem staging (coalesced)
// with transposed [d][row] layout (stride 33, conflict-free); in-block tree
// reduction over segments; epilogue on warp 0.

#define FMA2(d, a, b, c) asm("fma.rn.f32x2 %0, %1, %2, %3;" : "=l"(d) : "l"(a), "l"(b), "l"(c))
#define MUL2(d, a, b)    asm("mul.rn.f32x2 %0, %1, %2;"     : "=l"(d) : "l"(a), "l"(b))
#define ADD2(d, a, b)    asm("add.rn.f32x2 %0, %1, %2;"     : "=l"(d) : "l"(a), "l"(b))
#define PACK2(d, lo, hi) asm("mov.b64 %0, {%1, %2};"        : "=l"(d) : "f"(lo), "f"(hi))

static constexpr int D        = 768;
static constexpr int P        = 20;
static constexpr int NROWS    = 16 * 512;      // 8192
static constexpr int RPB      = 32;            // rows per block
static constexpr int NSUB     = 8;             // D-segments per row
static constexpr int THREADS  = RPB * NSUB;    // 256
static constexpr int CHUNK    = 32;            // d's staged per chunk
static constexpr int NCHUNK   = D / CHUNK;     // 24
static constexpr int DPT      = 4;             // d's per thread per chunk (CHUNK/NSUB)
static constexpr int TILE_STRIDE = 33;         // smem pad (odd -> conflict free)
static constexpr int TILE_ELEMS  = CHUNK * TILE_STRIDE;   // 1056

// smem layout (dynamic):
//   [0, 61440)              float s_w2[768*20]   (p-pairs adjacent; aliased by s_red later)
//   [61440, 61440+8448*2)   float s_r[2][1056], then s_m[2][1056]
static constexpr int SMEM_W2_BYTES  = D * P * 4;               // 61440
static constexpr int SMEM_TILE_OFF  = SMEM_W2_BYTES;
static constexpr int SMEM_TILE_B    = 2 * TILE_ELEMS * 4;      // 8448 per array
static constexpr int SMEM_TOTAL     = SMEM_TILE_OFF + 2 * SMEM_TILE_B; // 78336

__global__ void __launch_bounds__(THREADS, 2)
amatch_kernel(const float* __restrict__ R, const float* __restrict__ Mx,
              const float* __restrict__ W, float* __restrict__ out)
{
    extern __shared__ char smem_raw[];
    float* s_w2 = reinterpret_cast<float*>(smem_raw);
    float* s_r  = reinterpret_cast<float*>(smem_raw + SMEM_TILE_OFF);
    float* s_m  = reinterpret_cast<float*>(smem_raw + SMEM_TILE_OFF + SMEM_TILE_B);
    unsigned long long* s_red = reinterpret_cast<unsigned long long*>(smem_raw); // alias (post main loop)

    const int tid = threadIdx.x;

    // ---- stage w^2 into smem, layout [d][p] so p-pairs are adjacent (16B aligned per 4) ----
    for (int o = tid; o < D * P; o += THREADS) {
        int d = o / P;
        int p = o - d * P;
        float v = W[p * D + d];
        s_w2[o] = v * v;
    }

    const int row = tid & 31;        // 0..31  (lane within warp = row)
    const int sub = tid >> 5;        // 0..7   (warp id = D-segment)
    const int row0 = blockIdx.x * RPB;

    // loader mapping: 8 consecutive threads cover one row's 32 staged d's (coalesced float4)
    const int lrow = tid >> 3;          // 0..31
    const int dgrp = (tid & 7) << 2;    // 0,4,...,28
    const size_t gbase = (size_t)(row0 + lrow) * D + dgrp;

    unsigned long long accD[10], accR[10], accM[10];
#pragma unroll
    for (int k = 0; k < 10; k++) { accD[k] = 0ull; accR[k] = 0ull; accM[k] = 0ull; }

    // ---- prologue: stage chunk 0 into buffer 0 (transposed [d][row], stride 33) ----
    {
        float4 r4 = *reinterpret_cast<const float4*>(R  + gbase);
        float4 m4 = *reinterpret_cast<const float4*>(Mx + gbase);
        float* dr = s_r;  // buf 0
        float* dm = s_m;
        dr[(dgrp + 0) * TILE_STRIDE + lrow] = r4.x;
        dr[(dgrp + 1) * TILE_STRIDE + lrow] = r4.y;
        dr[(dgrp + 2) * TILE_STRIDE + lrow] = r4.z;
        dr[(dgrp + 3) * TILE_STRIDE + lrow] = r4.w;
        dm[(dgrp + 0) * TILE_STRIDE + lrow] = m4.x;
        dm[(dgrp + 1) * TILE_STRIDE + lrow] = m4.y;
        dm[(dgrp + 2) * TILE_STRIDE + lrow] = m4.z;
        dm[(dgrp + 3) * TILE_STRIDE + lrow] = m4.w;
    }
    __syncthreads();   // covers w2 fill + chunk 0

    const int d0 = sub * DPT;   // local d base within a chunk for this thread

    for (int c = 0; c < NCHUNK; ++c) {
        const int buf  = c & 1;
        const int nbuf = buf ^ 1;

        // stage next chunk into the other buffer (safe: its previous consumer
        // finished before the sync at the end of the prior iteration)
        if (c + 1 < NCHUNK) {
            const size_t gb = gbase + (size_t)(c + 1) * CHUNK;
            float4 r4 = *reinterpret_cast<const float4*>(R  + gb);
            float4 m4 = *reinterpret_cast<const float4*>(Mx + gb);
            float* dr = s_r + nbuf * TILE_ELEMS;
            float* dm = s_m + nbuf * TILE_ELEMS;
            dr[(dgrp + 0) * TILE_STRIDE + lrow] = r4.x;
            dr[(dgrp + 1) * TILE_STRIDE + lrow] = r4.y;
            dr[(dgrp + 2) * TILE_STRIDE + lrow] = r4.z;
            dr[(dgrp + 3) * TILE_STRIDE + lrow] = r4.w;
            dm[(dgrp + 0) * TILE_STRIDE + lrow] = m4.x;
            dm[(dgrp + 1) * TILE_STRIDE + lrow] = m4.y;
            dm[(dgrp + 2) * TILE_STRIDE + lrow] = m4.z;
            dm[(dgrp + 3) * TILE_STRIDE + lrow] = m4.w;
        }

        // ---- compute on current buffer ----
        const float* cr = s_r + buf * TILE_ELEMS;
        const float* cm = s_m + buf * TILE_ELEMS;

        float rv[DPT], mv[DPT];
#pragma unroll
        for (int i = 0; i < DPT; i++) {
            rv[i] = cr[(d0 + i) * TILE_STRIDE + row];
            mv[i] = cm[(d0 + i) * TILE_STRIDE + row];
        }

#pragma unroll
        for (int i = 0; i < DPT; i++) {
            unsigned long long rp, mp, rm2, rr2, mm2;
            PACK2(rp, rv[i], rv[i]);
            PACK2(mp, mv[i], mv[i]);
            MUL2(rm2, rp, mp);
            MUL2(rr2, rp, rp);
            MUL2(mm2, mp, mp);

            const int d = c * CHUNK + d0 + i;
            const ulonglong2* wrow = reinterpret_cast<const ulonglong2*>(s_w2 + d * P);
#pragma unroll
            for (int j = 0; j < 5; j++) {
                ulonglong2 wp = wrow[j];   // LDS.128: w2 pairs (4j,4j+1) and (4j+2,4j+3)
                FMA2(accD[2 * j],     rm2, wp.x, accD[2 * j]);
                FMA2(accD[2 * j + 1], rm2, wp.y, accD[2 * j + 1]);
                FMA2(accR[2 * j],     rr2, wp.x, accR[2 * j]);
                FMA2(accR[2 * j + 1], rr2, wp.y, accR[2 * j + 1]);
                FMA2(accM[2 * j],     mm2, wp.x, accM[2 * j]);
                FMA2(accM[2 * j + 1], mm2, wp.y, accM[2 * j + 1]);
            }
        }
        __syncthreads();
    }

    // ---- tree reduction over the 8 segments (smem layout [slot][k][row], conflict-free) ----
#pragma unroll
    for (int step = 4; step >= 1; step >>= 1) {
        if (sub >= step && sub < 2 * step) {
            const int slot = sub - step;
            unsigned long long* dst = s_red + (size_t)slot * (30 * 32) + row;
#pragma unroll
            for (int k = 0; k < 10; k++) {
                dst[(k)      * 32] = accD[k];
                dst[(10 + k) * 32] = accR[k];
                dst[(20 + k) * 32] = accM[k];
            }
        }
        __syncthreads();
        if (sub < step) {
            const unsigned long long* src = s_red + (size_t)sub * (30 * 32) + row;
#pragma unroll
            for (int k = 0; k < 10; k++) {
                ADD2(accD[k], accD[k], src[(k)      * 32]);
                ADD2(accR[k], accR[k], src[(10 + k) * 32]);
                ADD2(accM[k], accM[k], src[(20 + k) * 32]);
            }
        }
        __syncthreads();
    }

    // ---- epilogue (warp 0: one thread per row) ----
    if (sub == 0) {
        const float EPS = 1e-8f;
        const int n = row0 + row;
        float vals[P];
#pragma unroll
        for (int k = 0; k < 10; k++) {
            float dlo = __uint_as_float((unsigned)(accD[k] & 0xffffffffu));
            float dhi = __uint_as_float((unsigned)(accD[k] >> 32));
            float rlo = __uint_as_float((unsigned)(accR[k] & 0xffffffffu));
            float rhi = __uint_as_float((unsigned)(accR[k] >> 32));
            float mlo = __uint_as_float((unsigned)(accM[k] & 0xffffffffu));
            float mhi = __uint_as_float((unsigned)(accM[k] >> 32));
            vals[2 * k]     = dlo / (fmaxf(sqrtf(rlo), EPS) * fmaxf(sqrtf(mlo), EPS));
            vals[2 * k + 1] = dhi / (fmaxf(sqrtf(rhi), EPS) * fmaxf(sqrtf(mhi), EPS));
        }
        float4* o4 = reinterpret_cast<float4*>(out + (size_t)n * P);   // 80B aligned (n*80)
#pragma unroll
        for (int q = 0; q < 5; q++) {
            o4[q] = make_float4(vals[4 * q], vals[4 * q + 1], vals[4 * q + 2], vals[4 * q + 3]);
        }
    }
}

extern "C" void kernel_launch(void* const* d_in, const int* in_sizes, int n_in,
                              void* d_out, int out_size)
{
    const float* repres  = (const float*)d_in[0];
    const float* max_att = (const float*)d_in[1];
    const float* weight  = (const float*)d_in[2];
    float* out = (float*)d_out;

    cudaFuncSetAttribute(amatch_kernel,
                         cudaFuncAttributeMaxDynamicSharedMemorySize, SMEM_TOTAL);

    dim3 grid(NROWS / RPB);   // 256 blocks
    dim3 block(THREADS);      // 256 threads
    amatch_kernel<<<grid, block, SMEM_TOTAL>>>(repres, max_att, weight, out);
}

// round 4
// speedup vs baseline: 2.1461x; 2.1461x over previous
#include <cuda_runtime.h>
#include <cstdint>

// AtteMatchLay via legacy mma.sync TF32 (HMMA, base sm_103-legal):
//   dot = (r*m) @ w2^T, n1^2 = (r*r) @ w2^T, n2^2 = (m*m) @ w2^T
//   cos = dot / (max(sqrt(n1^2),eps) * max(sqrt(n2^2),eps))
// 256 CTAs x 32 rows. 8 warps = 2 row-strips x 4 K-quarters.
// Per warp: m16n8k8 tf32 MMAs, 3 A-types x 3 n-tiles (N padded 20->24),
// 36 f32 register accumulators. A chunks (64 K) double-buffered in smem,
// products computed in registers with cvt.rna.tf32. B (w2) built once in smem.

static constexpr int D        = 768;
static constexpr int P        = 20;
static constexpr int NPAD     = 24;          // 3 n-tiles of 8
static constexpr int ROWS_CTA = 32;
static constexpr int THREADS  = 256;
static constexpr int NROWS    = 8192;
static constexpr int NCTA     = NROWS / ROWS_CTA;   // 256
static constexpr int KCH      = 64;                 // K per staged chunk
static constexpr int NCHUNK   = D / KCH;            // 12

static constexpr int SB = 772;   // B smem row stride (floats): bank = 4n+k -> conflict-free
static constexpr int SA = 68;    // A smem row stride (floats): bank = 4row+k -> conflict-free

static constexpr int OFF_B   = 0;
static constexpr int B_BYTES = NPAD * SB * 4;            // 74112
static constexpr int OFF_A   = B_BYTES;                  // 74112 (16B aligned)
static constexpr int A_ARR   = ROWS_CTA * SA * 4;        // 8704 per {buf,array}
static constexpr int SMEM_TOTAL = OFF_A + 4 * A_ARR;     // 108928 -> 2 CTAs/SM
static constexpr int OFF_RED = OFF_A;                    // alias after mainloop (27648 B)
static constexpr int OFF_OUT = OFF_B;                    // alias after mainloop (2560 B)

__device__ __forceinline__ uint32_t f2tf32(float x) {
    uint32_t t;
    asm("cvt.rna.tf32.f32 %0, %1;" : "=r"(t) : "f"(x));
    return t;
}

__device__ __forceinline__ void mma8(float* d, const uint32_t* a, uint32_t b0, uint32_t b1) {
    asm volatile(
        "mma.sync.aligned.m16n8k8.row.col.f32.tf32.tf32.f32 "
        "{%0,%1,%2,%3}, {%4,%5,%6,%7}, {%8,%9}, {%0,%1,%2,%3};"
        : "+f"(d[0]), "+f"(d[1]), "+f"(d[2]), "+f"(d[3])
        : "r"(a[0]), "r"(a[1]), "r"(a[2]), "r"(a[3]), "r"(b0), "r"(b1));
}

__global__ void __launch_bounds__(THREADS, 2)
amatch_mma(const float* __restrict__ R, const float* __restrict__ Mx,
           const float* __restrict__ W, float* __restrict__ out)
{
    extern __shared__ char smem[];
    float* s_b = reinterpret_cast<float*>(smem + OFF_B);

    const int tid   = threadIdx.x;
    const int lane  = tid & 31;
    const int wid   = tid >> 5;
    const int g     = lane >> 2;       // groupID (row / n-col selector)
    const int t     = lane & 3;        // threadID-in-group (k selector)
    const int strip = wid >> 2;        // 0/1: which 16-row strip
    const int kq    = wid & 3;         // K quarter (48 K per chunk-half... 16 K per chunk)
    const int row0  = blockIdx.x * ROWS_CTA;

    // ---- build B = tf32(w^2), padded [24][772], rows 20..23 zero ----
    {
        const float4* w4 = reinterpret_cast<const float4*>(W);
        for (int i = tid; i < NPAD * (D / 4); i += THREADS) {
            const int n  = i / (D / 4);
            const int k4 = i - n * (D / 4);
            float4 v = (n < P) ? w4[n * (D / 4) + k4] : make_float4(0.f, 0.f, 0.f, 0.f);
            uint4 u;
            u.x = f2tf32(v.x * v.x); u.y = f2tf32(v.y * v.y);
            u.z = f2tf32(v.z * v.z); u.w = f2tf32(v.w * v.w);
            *reinterpret_cast<uint4*>(s_b + n * SB + k4 * 4) = u;
        }
    }

    // ---- A chunk stager: [32 rows][64 k] of r and m, stride 68 ----
    auto stage = [&](int c, int buf) {
        const float* gr = R  + (size_t)row0 * D + c * KCH;
        const float* gm = Mx + (size_t)row0 * D + c * KCH;
        float* sr = reinterpret_cast<float*>(smem + OFF_A + (buf * 2 + 0) * A_ARR);
        float* sm = reinterpret_cast<float*>(smem + OFF_A + (buf * 2 + 1) * A_ARR);
#pragma unroll
        for (int i = 0; i < 2; i++) {
            const int idx = i * THREADS + tid;   // 0..511
            const int row = idx >> 4;            // 16 float4 per row
            const int k4  = idx & 15;
            float4 rv = *reinterpret_cast<const float4*>(gr + (size_t)row * D + k4 * 4);
            float4 mv = *reinterpret_cast<const float4*>(gm + (size_t)row * D + k4 * 4);
            *reinterpret_cast<float4*>(sr + row * SA + k4 * 4) = rv;
            *reinterpret_cast<float4*>(sm + row * SA + k4 * 4) = mv;
        }
    };

    float acc[3][3][4];   // [type: rm/rr/mm][ntile][cfrag]
#pragma unroll
    for (int a = 0; a < 3; a++)
#pragma unroll
        for (int b = 0; b < 3; b++)
#pragma unroll
            for (int j = 0; j < 4; j++) acc[a][b][j] = 0.f;

    stage(0, 0);
    __syncthreads();

    for (int c = 0; c < NCHUNK; ++c) {
        const int buf = c & 1;
        if (c + 1 < NCHUNK) stage(c + 1, buf ^ 1);

        const float* sr = reinterpret_cast<float*>(smem + OFF_A + (buf * 2 + 0) * A_ARR);
        const float* sm = reinterpret_cast<float*>(smem + OFF_A + (buf * 2 + 1) * A_ARR);

#pragma unroll
        for (int it = 0; it < 2; it++) {
            const int kl  = kq * 16 + it * 8 + t;   // k within chunk (this thread's col)
            const int kgl = c * KCH + kl;           // global k (for B)

            const int i0 = (strip * 16 + g) * SA + kl;
            const int i1 = i0 + 8 * SA;
            const float r0 = sr[i0], r1 = sr[i1], r2 = sr[i0 + 4], r3 = sr[i1 + 4];
            const float m0 = sm[i0], m1 = sm[i1], m2 = sm[i0 + 4], m3 = sm[i1 + 4];

            uint32_t arm[4] = { f2tf32(r0 * m0), f2tf32(r1 * m1), f2tf32(r2 * m2), f2tf32(r3 * m3) };
            uint32_t arr[4] = { f2tf32(r0 * r0), f2tf32(r1 * r1), f2tf32(r2 * r2), f2tf32(r3 * r3) };
            uint32_t amm[4] = { f2tf32(m0 * m0), f2tf32(m1 * m1), f2tf32(m2 * m2), f2tf32(m3 * m3) };

#pragma unroll
            for (int nt = 0; nt < 3; nt++) {
                const int bi = (nt * 8 + g) * SB + kgl;
                const uint32_t b0 = __float_as_uint(s_b[bi]);
                const uint32_t b1 = __float_as_uint(s_b[bi + 4]);
                mma8(acc[0][nt], arm, b0, b1);
                mma8(acc[1][nt], arr, b0, b1);
                mma8(acc[2][nt], amm, b0, b1);
            }
        }
        __syncthreads();
    }

    // ---- reduce over the 4 K-quarter warps per strip (smem, conflict-free) ----
    float* s_red = reinterpret_cast<float*>(smem + OFF_RED);
    if (kq > 0) {
        float* dst = s_red + (size_t)(strip * 3 + (kq - 1)) * 36 * 32 + lane;
#pragma unroll
        for (int a = 0; a < 3; a++)
#pragma unroll
            for (int b = 0; b < 3; b++)
#pragma unroll
                for (int j = 0; j < 4; j++)
                    dst[((a * 3 + b) * 4 + j) * 32] = acc[a][b][j];
    }
    __syncthreads();

    float* s_out = reinterpret_cast<float*>(smem + OFF_OUT);
    if (kq == 0) {
#pragma unroll
        for (int s2 = 0; s2 < 3; s2++) {
            const float* src = s_red + (size_t)(strip * 3 + s2) * 36 * 32 + lane;
#pragma unroll
            for (int a = 0; a < 3; a++)
#pragma unroll
                for (int b = 0; b < 3; b++)
#pragma unroll
                    for (int j = 0; j < 4; j++)
                        acc[a][b][j] += src[((a * 3 + b) * 4 + j) * 32];
        }
        const float EPS = 1e-8f;
#pragma unroll
        for (int nt = 0; nt < 3; nt++) {
#pragma unroll
            for (int j = 0; j < 4; j++) {
                const int col = nt * 8 + 2 * t + (j & 1);
                const int row = strip * 16 + g + (j >> 1) * 8;
                if (col < P) {
                    const float dot = acc[0][nt][j];
                    const float a2  = acc[1][nt][j];
                    const float b2  = acc[2][nt][j];
                    s_out[row * P + col] =
                        dot / (fmaxf(sqrtf(a2), EPS) * fmaxf(sqrtf(b2), EPS));
                }
            }
        }
    }
    __syncthreads();

    // ---- coalesced store: 640 floats = 160 float4 ----
    if (tid < ROWS_CTA * P / 4) {
        float4 v = *reinterpret_cast<float4*>(s_out + tid * 4);
        *reinterpret_cast<float4*>(out + (size_t)row0 * P + tid * 4) = v;
    }
}

extern "C" void kernel_launch(void* const* d_in, const int* in_sizes, int n_in,
                              void* d_out, int out_size)
{
    const float* repres  = (const float*)d_in[0];
    const float* max_att = (const float*)d_in[1];
    const float* weight  = (const float*)d_in[2];
    float* out = (float*)d_out;

    cudaFuncSetAttribute(amatch_mma,
                         cudaFuncAttributeMaxDynamicSharedMemorySize, SMEM_TOTAL);

    amatch_mma<<<NCTA, THREADS, SMEM_TOTAL>>>(repres, max_att, weight, out);
}

// round 7
// speedup vs baseline: 2.1820x; 1.0167x over previous
#include <cuda_runtime.h>
#include <cstdint>

// AtteMatchLay via mma.sync TF32 + 4-deep cp.async pipeline.
//   dot = (r*m) @ w2^T, n1^2 = (r*r) @ w2^T, n2^2 = (m*m) @ w2^T
//   cos = dot / (max(sqrt(n1^2),eps) * max(sqrt(n2^2),eps))
// 256 CTAs x 32 rows, 8 warps = 2 row-strips x 4 K-quarters.
// Per chunk (64 K): cp.async stages r, m ([32][68] padded) and w2 slice
// ([64][24], from a prepped tf32 global buffer) -> 23552 B/stage, 4 stages.
// Products computed in registers (cvt.rna.tf32), 9 m16n8k8 MMAs per half-chunk.
// R6 fix: B-slice staging loops over all 384 float4s (256-thread block was
// only staging the first 256 -> rel_err 0.70).

static constexpr int D        = 768;
static constexpr int P        = 20;
static constexpr int NPAD     = 24;
static constexpr int ROWS_CTA = 32;
static constexpr int THREADS  = 256;
static constexpr int NROWS    = 8192;
static constexpr int NCTA     = NROWS / ROWS_CTA;   // 256
static constexpr int KCH      = 64;
static constexpr int NCHUNK   = D / KCH;            // 12
static constexpr int STAGES   = 4;

static constexpr int SA = 68;                        // A row stride (floats), conflict-free
static constexpr int A_ARR   = ROWS_CTA * SA * 4;    // 8704 B
static constexpr int B_ARR   = KCH * NPAD * 4;       // 6144 B
static constexpr int STG_B   = 2 * A_ARR + B_ARR;    // 23552 B
static constexpr int SMEM_TOTAL = STAGES * STG_B;    // 94208 -> 2 CTAs/SM

// epilogue aliases (after mainloop + syncthreads)
static constexpr int OFF_RED = 0;       // 2*3*36*32*4 = 27648 B
static constexpr int OFF_OUT = 28672;   // 32*20*4 = 2560 B

// prepped B: tf32(w^2) in [k][24] layout (cols 20..23 zero)
__device__ uint32_t w2t[D * NPAD];

__device__ __forceinline__ uint32_t f2tf32(float x) {
    uint32_t t;
    asm("cvt.rna.tf32.f32 %0, %1;" : "=r"(t) : "f"(x));
    return t;
}
__device__ __forceinline__ uint32_t smem_u32(const void* p) {
    uint32_t a;
    asm("{ .reg .u64 t; cvta.to.shared.u64 t, %1; cvt.u32.u64 %0, t; }" : "=r"(a) : "l"(p));
    return a;
}
__device__ __forceinline__ void cp16(uint32_t dst, const void* src) {
    asm volatile("cp.async.cg.shared.global [%0], [%1], 16;" :: "r"(dst), "l"(src));
}
__device__ __forceinline__ void cp_commit() {
    asm volatile("cp.async.commit_group;" ::: "memory");
}
template <int N>
__device__ __forceinline__ void cp_wait() {
    asm volatile("cp.async.wait_group %0;" :: "n"(N) : "memory");
}
__device__ __forceinline__ void mma8(float* d, const uint32_t* a, uint32_t b0, uint32_t b1) {
    asm volatile(
        "mma.sync.aligned.m16n8k8.row.col.f32.tf32.tf32.f32 "
        "{%0,%1,%2,%3}, {%4,%5,%6,%7}, {%8,%9}, {%0,%1,%2,%3};"
        : "+f"(d[0]), "+f"(d[1]), "+f"(d[2]), "+f"(d[3])
        : "r"(a[0]), "r"(a[1]), "r"(a[2]), "r"(a[3]), "r"(b0), "r"(b1));
}

// ---------------- prep kernel: w2t[k][n] = tf32(W[n][k]^2) ----------------
__global__ void w2_prep(const float* __restrict__ W) {
    int idx = blockIdx.x * blockDim.x + threadIdx.x;
    if (idx >= D * NPAD) return;
    int k = idx / NPAD;
    int n = idx - k * NPAD;
    float v = (n < P) ? W[n * D + k] : 0.0f;
    w2t[idx] = f2tf32(v * v);
}

// ---------------- main kernel ----------------
__global__ void __launch_bounds__(THREADS, 2)
amatch_mma(const float* __restrict__ R, const float* __restrict__ Mx,
           float* __restrict__ out)
{
    extern __shared__ char smem[];
    const uint32_t sb = smem_u32(smem);

    const int tid   = threadIdx.x;
    const int lane  = tid & 31;
    const int wid   = tid >> 5;
    const int g     = lane >> 2;
    const int t     = lane & 3;
    const int strip = wid >> 2;
    const int kq    = wid & 3;
    const int row0  = blockIdx.x * ROWS_CTA;

    // staging thread mapping (A): 512 float4 per array per chunk, 2 per thread
    const int srow0 = tid >> 4;          // rows tid>>4 and tid>>4 + 16
    const int sk4   = (tid & 15) << 2;   // k offset in floats (0,4,...,60)

    auto issue_stage = [&](int c, int s) {
        const uint32_t stg = sb + s * STG_B;
        const size_t gofs = (size_t)row0 * D + c * KCH;
        // A: r and m, 2 rows per thread
#pragma unroll
        for (int i = 0; i < 2; i++) {
            const int row = srow0 + i * 16;
            const size_t go = gofs + (size_t)row * D + sk4;
            const uint32_t so = (uint32_t)(row * SA + sk4) * 4u;
            cp16(stg + so,         R  + go);
            cp16(stg + A_ARR + so, Mx + go);
        }
        // B: 384 float4 over 256 threads (strided)
#pragma unroll
        for (int i = tid; i < B_ARR / 16; i += THREADS) {
            cp16(stg + 2 * A_ARR + i * 16, w2t + c * (KCH * NPAD) + i * 4);
        }
    };

    float acc[3][3][4];
#pragma unroll
    for (int a = 0; a < 3; a++)
#pragma unroll
        for (int b = 0; b < 3; b++)
#pragma unroll
            for (int j = 0; j < 4; j++) acc[a][b][j] = 0.f;

    // prologue: fill stages 0..2
#pragma unroll
    for (int s = 0; s < STAGES - 1; s++) {
        issue_stage(s, s);
        cp_commit();
    }

    for (int c = 0; c < NCHUNK; ++c) {
        // chunk c complete when pending groups <= min(2, 11-c)
        if (c <= NCHUNK - 3)      cp_wait<2>();
        else if (c == NCHUNK - 2) cp_wait<1>();
        else                      cp_wait<0>();
        __syncthreads();

        if (c + STAGES - 1 < NCHUNK) {
            issue_stage(c + STAGES - 1, (c + STAGES - 1) & (STAGES - 1));
            cp_commit();
        }

        const char* stg = smem + (c & (STAGES - 1)) * STG_B;
        const float* sr = reinterpret_cast<const float*>(stg);
        const float* sm = reinterpret_cast<const float*>(stg + A_ARR);
        const float* sw = reinterpret_cast<const float*>(stg + 2 * A_ARR);

#pragma unroll
        for (int it = 0; it < 2; it++) {
            const int kl = kq * 16 + it * 8 + t;

            const int i0 = (strip * 16 + g) * SA + kl;
            const int i1 = i0 + 8 * SA;
            const float r0 = sr[i0], r1 = sr[i1], r2 = sr[i0 + 4], r3 = sr[i1 + 4];
            const float m0 = sm[i0], m1 = sm[i1], m2 = sm[i0 + 4], m3 = sm[i1 + 4];

            uint32_t arm[4] = { f2tf32(r0 * m0), f2tf32(r1 * m1), f2tf32(r2 * m2), f2tf32(r3 * m3) };
            uint32_t arr[4] = { f2tf32(r0 * r0), f2tf32(r1 * r1), f2tf32(r2 * r2), f2tf32(r3 * r3) };
            uint32_t amm[4] = { f2tf32(m0 * m0), f2tf32(m1 * m1), f2tf32(m2 * m2), f2tf32(m3 * m3) };

#pragma unroll
            for (int nt = 0; nt < 3; nt++) {
                const uint32_t b0 = __float_as_uint(sw[kl * NPAD + nt * 8 + g]);
                const uint32_t b1 = __float_as_uint(sw[(kl + 4) * NPAD + nt * 8 + g]);
                mma8(acc[0][nt], arm, b0, b1);
                mma8(acc[1][nt], arr, b0, b1);
                mma8(acc[2][nt], amm, b0, b1);
            }
        }
    }
    __syncthreads();   // all warps done with stage buffers before aliasing

    // ---- reduce over the 4 K-quarter warps per strip ----
    float* s_red = reinterpret_cast<float*>(smem + OFF_RED);
    if (kq > 0) {
        float* dst = s_red + (size_t)(strip * 3 + (kq - 1)) * 36 * 32 + lane;
#pragma unroll
        for (int a = 0; a < 3; a++)
#pragma unroll
            for (int b = 0; b < 3; b++)
#pragma unroll
                for (int j = 0; j < 4; j++)
                    dst[((a * 3 + b) * 4 + j) * 32] = acc[a][b][j];
    }
    __syncthreads();

    float* s_out = reinterpret_cast<float*>(smem + OFF_OUT);
    if (kq == 0) {
#pragma unroll
        for (int s2 = 0; s2 < 3; s2++) {
            const float* src = s_red + (size_t)(strip * 3 + s2) * 36 * 32 + lane;
#pragma unroll
            for (int a = 0; a < 3; a++)
#pragma unroll
                for (int b = 0; b < 3; b++)
#pragma unroll
                    for (int j = 0; j < 4; j++)
                        acc[a][b][j] += src[((a * 3 + b) * 4 + j) * 32];
        }
        const float EPS = 1e-8f;
#pragma unroll
        for (int nt = 0; nt < 3; nt++) {
#pragma unroll
            for (int j = 0; j < 4; j++) {
                const int col = nt * 8 + 2 * t + (j & 1);
                const int row = strip * 16 + g + (j >> 1) * 8;
                if (col < P) {
                    const float dot = acc[0][nt][j];
                    const float a2  = acc[1][nt][j];
                    const float b2  = acc[2][nt][j];
                    s_out[row * P + col] =
                        dot / (fmaxf(sqrtf(a2), EPS) * fmaxf(sqrtf(b2), EPS));
                }
            }
        }
    }
    __syncthreads();

    if (tid < ROWS_CTA * P / 4) {
        float4 v = *reinterpret_cast<float4*>(s_out + tid * 4);
        *reinterpret_cast<float4*>(out + (size_t)row0 * P + tid * 4) = v;
    }
}

extern "C" void kernel_launch(void* const* d_in, const int* in_sizes, int n_in,
                              void* d_out, int out_size)
{
    const float* repres  = (const float*)d_in[0];
    const float* max_att = (const float*)d_in[1];
    const float* weight  = (const float*)d_in[2];
    float* out = (float*)d_out;

    cudaFuncSetAttribute(amatch_mma,
                         cudaFuncAttributeMaxDynamicSharedMemorySize, SMEM_TOTAL);

    w2_prep<<<(D * NPAD + 255) / 256, 256>>>(weight);
    amatch_mma<<<NCTA, THREADS, SMEM_TOTAL>>>(repres, max_att, out);
}